// round 8
// baseline (speedup 1.0000x reference)
#include <cuda_runtime.h>
#include <cstdint>
#include <cstddef>

#define NN   8192
#define FIN  256
#define FOUT 64
#define CAP2 128          // per-row neighbor list capacity (mean 32, 11+ sigma safe)
#define PROJ_BLOCKS 256
#define SCAN_BLOCKS 2048  // each owns 8192 contiguous uint4 (128KB)

__device__ float g_fts[(size_t)NN * FOUT];
__device__ float g_f1[NN];
__device__ float g_f2[NN];
__device__ int   g_cnt[NN];            // zero-init at load; reset by agg_kernel
__device__ int   g_lst[(size_t)NN * CAP2];

__device__ __forceinline__ float lrelu(float v) { return fmaxf(v, 0.2f * v); }

__device__ __forceinline__ unsigned long long pack2(float lo, float hi) {
    unsigned long long r;
    asm("mov.b64 %0, {%1, %2};" : "=l"(r) : "f"(lo), "f"(hi));
    return r;
}
__device__ __forceinline__ unsigned long long ffma2(unsigned long long a,
                                                    unsigned long long b,
                                                    unsigned long long c) {
    unsigned long long d;
    asm("fma.rn.f32x2 %0, %1, %2, %3;" : "=l"(d) : "l"(a), "l"(b), "l"(c));
    return d;
}
__device__ __forceinline__ float2 unpack2(unsigned long long v) {
    float2 f;
    asm("mov.b64 {%0, %1}, %2;" : "=f"(f.x), "=f"(f.y) : "l"(v));
    return f;
}

// ---------------------------------------------------------------------------
// Fused kernel: blocks [0, PROJ_BLOCKS) = projection GEMM (FFMA-bound),
// blocks [PROJ_BLOCKS, +SCAN_BLOCKS) = streaming adjacency compaction over a
// CONTIGUOUS 128KB segment per block, double-buffered loads.
// ---------------------------------------------------------------------------
__global__ void __launch_bounds__(256) fused_kernel(
    const float* __restrict__ x, const float* __restrict__ W,
    const float* __restrict__ a1, const float* __restrict__ b1,
    const float* __restrict__ a2, const float* __restrict__ b2,
    const float* __restrict__ adj)
{
    const int tid = threadIdx.x;

    if (blockIdx.x >= PROJ_BLOCKS) {
        // ======== scan: contiguous segment, double-buffered ========
        const int base = (blockIdx.x - PROJ_BLOCKS) * 8192;   // uint4 index
        const uint4* a4 = (const uint4*)adj + base + tid;

        uint4 v[2][8];
#pragma unroll
        for (int k = 0; k < 8; ++k)
            v[0][k] = __ldcs(a4 + k * 256);

#pragma unroll
        for (int it = 0; it < 4; ++it) {
            const int cur = it & 1;
            if (it < 3) {
#pragma unroll
                for (int k = 0; k < 8; ++k)
                    v[cur ^ 1][k] = __ldcs(a4 + ((it + 1) * 8 + k) * 256);
            }
#pragma unroll
            for (int k = 0; k < 8; ++k) {
                const uint4 w = v[cur][k];
                unsigned m = ((~w.x) >> 31)
                           | (((~w.y) >> 31) << 1)
                           | (((~w.z) >> 31) << 2)
                           | (((~w.w) >> 31) << 3);
                if (m) {
                    const int idx = base + tid + (it * 8 + k) * 256;
                    const int row = idx >> 11;          // 2048 uint4 per row
                    const int col = (idx & 2047) * 4;
                    int b = atomicAdd(&g_cnt[row], __popc(m));
                    while (m) {
                        const int q = __ffs(m) - 1;
                        m &= m - 1;
                        if (b < CAP2) g_lst[(size_t)row * CAP2 + b] = col + q;
                        ++b;
                    }
                }
            }
        }
        return;
    }

    // ======== proj: 32 rows x 64 cols per block, K-chunks of 32 ========
    {
        __shared__ __align__(16) float xsT[32 * 34];   // [k][row] pad 34
        __shared__ __align__(16) float Ws[32 * 64];    // [k][col]

        const int rowg = tid >> 4;       // 0..15 -> rows r0,r0+1
        const int colg = tid & 15;       // 0..15 -> 4 cols
        const int r0   = rowg * 2;
        const int f0   = colg * 4;
        const int rb   = blockIdx.x * 32;

        const int xrow = tid >> 3;       // 0..31
        const int xkq  = tid & 7;        // float4 along k
        const float4* xg = (const float4*)(x + (size_t)(rb + xrow) * FIN) + xkq;
        const float4* W4 = (const float4*)W;
        float4* Ws4 = (float4*)Ws;

        float4 gx, gw0, gw1;
        unsigned long long acc[4];
#pragma unroll
        for (int t = 0; t < 4; ++t) acc[t] = 0ull;

        // prologue chunk 0
        gx  = xg[0];
        gw0 = W4[tid];
        gw1 = W4[tid + 256];
        xsT[(xkq * 4 + 0) * 34 + xrow] = gx.x;
        xsT[(xkq * 4 + 1) * 34 + xrow] = gx.y;
        xsT[(xkq * 4 + 2) * 34 + xrow] = gx.z;
        xsT[(xkq * 4 + 3) * 34 + xrow] = gx.w;
        Ws4[tid]       = gw0;
        Ws4[tid + 256] = gw1;
        __syncthreads();

        for (int c = 0; c < 8; ++c) {
            if (c < 7) {
                gx  = xg[(c + 1) * 8];
                gw0 = W4[(c + 1) * 512 + tid];
                gw1 = W4[(c + 1) * 512 + tid + 256];
            }
#pragma unroll
            for (int k = 0; k < 32; ++k) {
                const float2 xv = *(const float2*)(xsT + k * 34 + r0);
                const unsigned long long xa = pack2(xv.x, xv.x);
                const unsigned long long xb = pack2(xv.y, xv.y);
                const ulonglong2 w = *(const ulonglong2*)(Ws + k * FOUT + f0);
                acc[0] = ffma2(xa, w.x, acc[0]);
                acc[1] = ffma2(xa, w.y, acc[1]);
                acc[2] = ffma2(xb, w.x, acc[2]);
                acc[3] = ffma2(xb, w.y, acc[3]);
            }
            if (c < 7) {
                __syncthreads();
                xsT[(xkq * 4 + 0) * 34 + xrow] = gx.x;
                xsT[(xkq * 4 + 1) * 34 + xrow] = gx.y;
                xsT[(xkq * 4 + 2) * 34 + xrow] = gx.z;
                xsT[(xkq * 4 + 3) * 34 + xrow] = gx.w;
                Ws4[tid]       = gw0;
                Ws4[tid + 256] = gw1;
                __syncthreads();
            }
        }

        const int rg0 = rb + r0;
        *(ulonglong2*)(g_fts + (size_t)rg0 * FOUT + f0)       = make_ulonglong2(acc[0], acc[1]);
        *(ulonglong2*)(g_fts + (size_t)(rg0 + 1) * FOUT + f0) = make_ulonglong2(acc[2], acc[3]);

        float p1r0 = 0.f, p2r0 = 0.f, p1r1 = 0.f, p2r1 = 0.f;
#pragma unroll
        for (int t = 0; t < 2; ++t) {
            const float2 v0 = unpack2(acc[t]);
            const float2 v1 = unpack2(acc[2 + t]);
            const float a1l = a1[f0 + 2 * t], a1h = a1[f0 + 2 * t + 1];
            const float a2l = a2[f0 + 2 * t], a2h = a2[f0 + 2 * t + 1];
            p1r0 += v0.x * a1l + v0.y * a1h;
            p2r0 += v0.x * a2l + v0.y * a2h;
            p1r1 += v1.x * a1l + v1.y * a1h;
            p2r1 += v1.x * a2l + v1.y * a2h;
        }
#pragma unroll
        for (int o = 1; o < 16; o <<= 1) {
            p1r0 += __shfl_xor_sync(0xffffffffu, p1r0, o);
            p2r0 += __shfl_xor_sync(0xffffffffu, p2r0, o);
            p1r1 += __shfl_xor_sync(0xffffffffu, p1r1, o);
            p2r1 += __shfl_xor_sync(0xffffffffu, p2r1, o);
        }
        if (colg == 0) {
            g_f1[rg0]     = p1r0 + b1[0];
            g_f2[rg0]     = p2r0 + b2[0];
            g_f1[rg0 + 1] = p1r1 + b1[0];
            g_f2[rg0 + 1] = p2r1 + b2[0];
        }
    }
}

// ---------------------------------------------------------------------------
// Aggregate: ONE WARP PER ROW, 4 rows / 128-thread block (grid=2048). No
// block barriers. Neighbor list loaded SPECULATIVELY (independent of cnt) to
// cut one DRAM round-trip from the serial chain; masked afterward.
// ---------------------------------------------------------------------------
__global__ void __launch_bounds__(128) agg_kernel(
    const float* __restrict__ adj, const float* __restrict__ bias,
    float* __restrict__ out)
{
    const int tid  = threadIdx.x;
    const int wid  = tid >> 5;
    const int lane = tid & 31;
    const int i    = blockIdx.x * 4 + wid;

    // issue cnt + list loads together (no dependency)
    const int cnt = g_cnt[i];
    int raw[4];
#pragma unroll
    for (int t = 0; t < 4; ++t)
        raw[t] = g_lst[(size_t)i * CAP2 + lane + 32 * t];
    if (lane == 0) g_cnt[i] = 0;        // reset after read, program order

    const float  f1i = g_f1[i];
    const float2 bv  = *(const float2*)(bias + 2 * lane);

    if (cnt > 0 && cnt <= CAP2) {
        int   jj[4];
        float ss[4];
#pragma unroll
        for (int t = 0; t < 4; ++t) {
            jj[t] = raw[t] & (NN - 1);
            ss[t] = (lane + 32 * t < cnt) ? lrelu(f1i + g_f2[jj[t]]) : -3.4e38f;
        }

        float m = fmaxf(fmaxf(ss[0], ss[1]), fmaxf(ss[2], ss[3]));
#pragma unroll
        for (int o = 16; o; o >>= 1) m = fmaxf(m, __shfl_xor_sync(0xffffffffu, m, o));

        float pp[4];
        float l = 0.f;
#pragma unroll
        for (int t = 0; t < 4; ++t) {
            pp[t] = (lane + 32 * t < cnt) ? __expf(ss[t] - m) : 0.f;
            l += pp[t];
        }
#pragma unroll
        for (int o = 16; o; o >>= 1) l += __shfl_xor_sync(0xffffffffu, l, o);

        // gather: static 32-wide unroll per register group (padded p=0)
        float A0 = 0.f, A1 = 0.f;
#pragma unroll
        for (int t = 0; t < 4; ++t) {
            if (cnt > 32 * t) {
#pragma unroll
                for (int src = 0; src < 32; ++src) {
                    const float pe = __shfl_sync(0xffffffffu, pp[t], src);
                    const int   je = __shfl_sync(0xffffffffu, jj[t], src);
                    const float2 fv = *(const float2*)(g_fts + (size_t)je * FOUT + 2 * lane);
                    A0 += pe * fv.x;
                    A1 += pe * fv.y;
                }
            }
        }

        const float inv = 1.f / l;
        const float v0 = A0 * inv + bv.x;
        const float v1 = A1 * inv + bv.y;
        float2 ov;
        ov.x = (v0 > 0.f) ? v0 : expm1f(v0);
        ov.y = (v1 > 0.f) ? v1 : expm1f(v1);
        *(float2*)(out + (size_t)i * FOUT + 2 * lane) = ov;
    } else {
        // exact slow path (empty row / overflow; P ~ 1e-14), warp-local
        const float* arow = adj + (size_t)i * NN;

        float m = -3.4e38f;
        for (int j = lane; j < NN; j += 32)
            m = fmaxf(m, lrelu(f1i + g_f2[j]) + arow[j]);
#pragma unroll
        for (int o = 16; o; o >>= 1) m = fmaxf(m, __shfl_xor_sync(0xffffffffu, m, o));

        float A0 = 0.f, A1 = 0.f, l = 0.f;
        for (int j0 = 0; j0 < NN; j0 += 32) {
            const float p = __expf(lrelu(f1i + g_f2[j0 + lane]) + arow[j0 + lane] - m);
            l += p;
#pragma unroll 1
            for (int src = 0; src < 32; ++src) {
                const float pe = __shfl_sync(0xffffffffu, p, src);
                if (pe > 0.f) {
                    const float2 fv = *(const float2*)(g_fts + (size_t)(j0 + src) * FOUT + 2 * lane);
                    A0 += pe * fv.x;
                    A1 += pe * fv.y;
                }
            }
        }
#pragma unroll
        for (int o = 16; o; o >>= 1) l += __shfl_xor_sync(0xffffffffu, l, o);

        const float v0 = A0 / l + bv.x;
        const float v1 = A1 / l + bv.y;
        float2 ov;
        ov.x = (v0 > 0.f) ? v0 : expm1f(v0);
        ov.y = (v1 > 0.f) ? v1 : expm1f(v1);
        *(float2*)(out + (size_t)i * FOUT + 2 * lane) = ov;
    }
}

// ---------------------------------------------------------------------------
extern "C" void kernel_launch(void* const* d_in, const int* in_sizes, int n_in,
                              void* d_out, int out_size)
{
    (void)in_sizes; (void)n_in; (void)out_size;
    const float* x    = (const float*)d_in[0];
    const float* adj  = (const float*)d_in[1];
    const float* W    = (const float*)d_in[2];
    const float* a1   = (const float*)d_in[3];
    const float* b1   = (const float*)d_in[4];
    const float* a2   = (const float*)d_in[5];
    const float* b2   = (const float*)d_in[6];
    const float* bias = (const float*)d_in[7];
    float* out = (float*)d_out;

    fused_kernel<<<PROJ_BLOCKS + SCAN_BLOCKS, 256>>>(x, W, a1, b1, a2, b2, adj);
    agg_kernel<<<NN / 4, 128>>>(adj, bias, out);
}

// round 9
// speedup vs baseline: 1.6130x; 1.6130x over previous
#include <cuda_runtime.h>
#include <cstdint>
#include <cstddef>

#define NN    8192
#define FIN   256
#define FOUT  64
#define CAPS  192          // per-row shared neighbor list capacity (mean 32)
#define PROJ_BLOCKS 256
#define SCAN_BLOCKS 2048   // each owns 4 complete rows (128KB contiguous)

__device__ float g_fts[(size_t)NN * FOUT];
__device__ float g_f1[NN];
__device__ float g_f2[NN];
__device__ int   g_proj_done;   // 0 at load; reset by last scan block
__device__ int   g_scan_done;

__device__ __forceinline__ float lrelu(float v) { return fmaxf(v, 0.2f * v); }

__device__ __forceinline__ unsigned long long pack2(float lo, float hi) {
    unsigned long long r;
    asm("mov.b64 %0, {%1, %2};" : "=l"(r) : "f"(lo), "f"(hi));
    return r;
}
__device__ __forceinline__ unsigned long long ffma2(unsigned long long a,
                                                    unsigned long long b,
                                                    unsigned long long c) {
    unsigned long long d;
    asm("fma.rn.f32x2 %0, %1, %2, %3;" : "=l"(d) : "l"(a), "l"(b), "l"(c));
    return d;
}
__device__ __forceinline__ float2 unpack2(unsigned long long v) {
    float2 f;
    asm("mov.b64 {%0, %1}, %2;" : "=f"(f.x), "=f"(f.y) : "l"(v));
    return f;
}

// ---------------------------------------------------------------------------
// ONE kernel. Blocks [0,256): projection GEMM, then release g_proj_done.
// Blocks [256, 256+2048): stream 4 complete adj rows (128KB) into shared
// neighbor lists, acquire proj results, then softmax+gather+ELU those 4 rows.
// The agg tail of each block overlaps other blocks' streaming.
// ---------------------------------------------------------------------------
__global__ void __launch_bounds__(256) fused_kernel(
    const float* __restrict__ x, const float* __restrict__ W,
    const float* __restrict__ a1, const float* __restrict__ b1,
    const float* __restrict__ a2, const float* __restrict__ b2,
    const float* __restrict__ adj, const float* __restrict__ bias,
    float* __restrict__ out)
{
    const int tid = threadIdx.x;

    if (blockIdx.x >= PROJ_BLOCKS) {
        // ==================== scan + per-row aggregate ====================
        __shared__ int   s_cnt[4];
        __shared__ int   s_lst[4][CAPS];
        __shared__ float s_p[4][CAPS];

        const int seg  = blockIdx.x - PROJ_BLOCKS;
        const int r0   = seg * 4;
        const int w    = tid >> 5;        // warp 0..7
        const int lane = tid & 31;
        const int rl   = w >> 1;          // local row 0..3 (2 warps per row)
        const int h    = w & 1;           // half of the row

        if (tid < 4) s_cnt[tid] = 0;
        __syncthreads();

        // warp streams 1024 contiguous uint4 (16KB): 4 iters x 8-deep batches
        const uint4* a4 = (const uint4*)adj
                        + (size_t)(r0 + rl) * 2048 + h * 1024 + lane;
        const int ubase = h * 1024 + lane;

#pragma unroll 1
        for (int it = 0; it < 4; ++it) {
            uint4 v[8];
#pragma unroll
            for (int k = 0; k < 8; ++k)
                v[k] = __ldcs(a4 + (it * 8 + k) * 32);
#pragma unroll
            for (int k = 0; k < 8; ++k) {
                unsigned m = ((~v[k].x) >> 31)
                           | (((~v[k].y) >> 31) << 1)
                           | (((~v[k].z) >> 31) << 2)
                           | (((~v[k].w) >> 31) << 3);
                if (m) {
                    const int col = (ubase + (it * 8 + k) * 32) * 4;
                    int b = atomicAdd(&s_cnt[rl], __popc(m));
                    while (m) {
                        const int q = __ffs(m) - 1;
                        m &= m - 1;
                        if (b < CAPS) s_lst[rl][b] = col + q;
                        ++b;
                    }
                }
            }
        }
        __syncthreads();                  // lists complete

        // acquire projection results
        if (tid == 0) {
            while (*(volatile int*)&g_proj_done < PROJ_BLOCKS) { }
            __threadfence();
        }
        __syncthreads();

        // ---- aggregate: warps 0..3, one row each ----
        if (w < 4) {
            const int   i   = r0 + w;
            const int   cnt = s_cnt[w];
            const float f1i = g_f1[i];
            const float2 bv = *(const float2*)(bias + 2 * lane);

            if (cnt > 0 && cnt <= CAPS) {
                // scores + warp max
                float mloc = -3.4e38f;
                for (int e = lane; e < cnt; e += 32) {
                    const float s = lrelu(f1i + g_f2[s_lst[w][e]]);
                    s_p[w][e] = s;
                    mloc = fmaxf(mloc, s);
                }
#pragma unroll
                for (int o = 16; o; o >>= 1)
                    mloc = fmaxf(mloc, __shfl_xor_sync(0xffffffffu, mloc, o));
                __syncwarp();

                // exp + sum; pad to multiple of 8 with zeros
                const int cpad = (cnt + 7) & ~7;
                float l = 0.f;
                for (int e = lane; e < cpad; e += 32) {
                    if (e < cnt) {
                        const float p = __expf(s_p[w][e] - mloc);
                        s_p[w][e] = p;
                        l += p;
                    } else {
                        s_p[w][e]   = 0.f;
                        s_lst[w][e] = 0;
                    }
                }
#pragma unroll
                for (int o = 16; o; o >>= 1)
                    l += __shfl_xor_sync(0xffffffffu, l, o);
                __syncwarp();

                // gather, 8-way unrolled (broadcast LDS + pipelined LDG)
                float A0 = 0.f, A1 = 0.f;
                for (int e0 = 0; e0 < cpad; e0 += 8) {
#pragma unroll
                    for (int u = 0; u < 8; ++u) {
                        const float p = s_p[w][e0 + u];
                        const int   j = s_lst[w][e0 + u];
                        const float2 fv = *(const float2*)(g_fts + (size_t)j * FOUT + 2 * lane);
                        A0 += p * fv.x;
                        A1 += p * fv.y;
                    }
                }

                const float inv = 1.f / l;
                const float v0 = A0 * inv + bv.x;
                const float v1 = A1 * inv + bv.y;
                float2 ov;
                ov.x = (v0 > 0.f) ? v0 : expm1f(v0);
                ov.y = (v1 > 0.f) ? v1 : expm1f(v1);
                *(float2*)(out + (size_t)i * FOUT + 2 * lane) = ov;
            } else {
                // exact slow path (empty row / overflow; astronomically rare)
                const float* arow = adj + (size_t)i * NN;
                float m = -3.4e38f;
                for (int j = lane; j < NN; j += 32)
                    m = fmaxf(m, lrelu(f1i + g_f2[j]) + arow[j]);
#pragma unroll
                for (int o = 16; o; o >>= 1)
                    m = fmaxf(m, __shfl_xor_sync(0xffffffffu, m, o));

                float A0 = 0.f, A1 = 0.f, l = 0.f;
                for (int j0 = 0; j0 < NN; j0 += 32) {
                    const float p = __expf(lrelu(f1i + g_f2[j0 + lane]) + arow[j0 + lane] - m);
                    l += p;
#pragma unroll 1
                    for (int src = 0; src < 32; ++src) {
                        const float pe = __shfl_sync(0xffffffffu, p, src);
                        if (pe > 0.f) {
                            const float2 fv = *(const float2*)(g_fts + (size_t)(j0 + src) * FOUT + 2 * lane);
                            A0 += pe * fv.x;
                            A1 += pe * fv.y;
                        }
                    }
                }
#pragma unroll
                for (int o = 16; o; o >>= 1)
                    l += __shfl_xor_sync(0xffffffffu, l, o);

                const float v0 = A0 / l + bv.x;
                const float v1 = A1 / l + bv.y;
                float2 ov;
                ov.x = (v0 > 0.f) ? v0 : expm1f(v0);
                ov.y = (v1 > 0.f) ? v1 : expm1f(v1);
                *(float2*)(out + (size_t)i * FOUT + 2 * lane) = ov;
            }
        }

        // last scan block resets flags for graph replay
        __syncthreads();
        if (tid == 0) {
            const int d = atomicAdd(&g_scan_done, 1);
            if (d == SCAN_BLOCKS - 1) {
                g_proj_done = 0;
                g_scan_done = 0;
            }
        }
        return;
    }

    // ==================== proj: 32 rows x 64 cols per block ====================
    {
        __shared__ __align__(16) float xsT[32 * 34];   // [k][row] pad 34
        __shared__ __align__(16) float Ws[32 * 64];    // [k][col]

        const int rowg = tid >> 4;
        const int colg = tid & 15;
        const int r0   = rowg * 2;
        const int f0   = colg * 4;
        const int rb   = blockIdx.x * 32;

        const int xrow = tid >> 3;
        const int xkq  = tid & 7;
        const float4* xg = (const float4*)(x + (size_t)(rb + xrow) * FIN) + xkq;
        const float4* W4 = (const float4*)W;
        float4* Ws4 = (float4*)Ws;

        float4 gx, gw0, gw1;
        unsigned long long acc[4];
#pragma unroll
        for (int t = 0; t < 4; ++t) acc[t] = 0ull;

        gx  = xg[0];
        gw0 = W4[tid];
        gw1 = W4[tid + 256];
        xsT[(xkq * 4 + 0) * 34 + xrow] = gx.x;
        xsT[(xkq * 4 + 1) * 34 + xrow] = gx.y;
        xsT[(xkq * 4 + 2) * 34 + xrow] = gx.z;
        xsT[(xkq * 4 + 3) * 34 + xrow] = gx.w;
        Ws4[tid]       = gw0;
        Ws4[tid + 256] = gw1;
        __syncthreads();

        for (int c = 0; c < 8; ++c) {
            if (c < 7) {
                gx  = xg[(c + 1) * 8];
                gw0 = W4[(c + 1) * 512 + tid];
                gw1 = W4[(c + 1) * 512 + tid + 256];
            }
#pragma unroll
            for (int k = 0; k < 32; ++k) {
                const float2 xv = *(const float2*)(xsT + k * 34 + r0);
                const unsigned long long xa = pack2(xv.x, xv.x);
                const unsigned long long xb = pack2(xv.y, xv.y);
                const ulonglong2 wv = *(const ulonglong2*)(Ws + k * FOUT + f0);
                acc[0] = ffma2(xa, wv.x, acc[0]);
                acc[1] = ffma2(xa, wv.y, acc[1]);
                acc[2] = ffma2(xb, wv.x, acc[2]);
                acc[3] = ffma2(xb, wv.y, acc[3]);
            }
            if (c < 7) {
                __syncthreads();
                xsT[(xkq * 4 + 0) * 34 + xrow] = gx.x;
                xsT[(xkq * 4 + 1) * 34 + xrow] = gx.y;
                xsT[(xkq * 4 + 2) * 34 + xrow] = gx.z;
                xsT[(xkq * 4 + 3) * 34 + xrow] = gx.w;
                Ws4[tid]       = gw0;
                Ws4[tid + 256] = gw1;
                __syncthreads();
            }
        }

        const int rg0 = rb + r0;
        *(ulonglong2*)(g_fts + (size_t)rg0 * FOUT + f0)       = make_ulonglong2(acc[0], acc[1]);
        *(ulonglong2*)(g_fts + (size_t)(rg0 + 1) * FOUT + f0) = make_ulonglong2(acc[2], acc[3]);

        float p1r0 = 0.f, p2r0 = 0.f, p1r1 = 0.f, p2r1 = 0.f;
#pragma unroll
        for (int t = 0; t < 2; ++t) {
            const float2 v0 = unpack2(acc[t]);
            const float2 v1 = unpack2(acc[2 + t]);
            const float a1l = a1[f0 + 2 * t], a1h = a1[f0 + 2 * t + 1];
            const float a2l = a2[f0 + 2 * t], a2h = a2[f0 + 2 * t + 1];
            p1r0 += v0.x * a1l + v0.y * a1h;
            p2r0 += v0.x * a2l + v0.y * a2h;
            p1r1 += v1.x * a1l + v1.y * a1h;
            p2r1 += v1.x * a2l + v1.y * a2h;
        }
#pragma unroll
        for (int o = 1; o < 16; o <<= 1) {
            p1r0 += __shfl_xor_sync(0xffffffffu, p1r0, o);
            p2r0 += __shfl_xor_sync(0xffffffffu, p2r0, o);
            p1r1 += __shfl_xor_sync(0xffffffffu, p1r1, o);
            p2r1 += __shfl_xor_sync(0xffffffffu, p2r1, o);
        }
        if (colg == 0) {
            g_f1[rg0]     = p1r0 + b1[0];
            g_f2[rg0]     = p2r0 + b2[0];
            g_f1[rg0 + 1] = p1r1 + b1[0];
            g_f2[rg0 + 1] = p2r1 + b2[0];
        }

        // release: all writes visible, then signal
        __threadfence();
        __syncthreads();
        if (tid == 0) atomicAdd(&g_proj_done, 1);
    }
}

// ---------------------------------------------------------------------------
extern "C" void kernel_launch(void* const* d_in, const int* in_sizes, int n_in,
                              void* d_out, int out_size)
{
    (void)in_sizes; (void)n_in; (void)out_size;
    const float* x    = (const float*)d_in[0];
    const float* adj  = (const float*)d_in[1];
    const float* W    = (const float*)d_in[2];
    const float* a1   = (const float*)d_in[3];
    const float* b1   = (const float*)d_in[4];
    const float* a2   = (const float*)d_in[5];
    const float* b2   = (const float*)d_in[6];
    const float* bias = (const float*)d_in[7];
    float* out = (float*)d_out;

    fused_kernel<<<PROJ_BLOCKS + SCAN_BLOCKS, 256>>>(x, W, a1, b1, a2, b2, adj, bias, out);
}